// round 15
// baseline (speedup 1.0000x reference)
#include <cuda_runtime.h>
#include <math.h>

#define NE   16
#define NU   8
#define NA   4
#define NSV  256
#define NPV  32
#define NFB  4
#define NDET 16
#define SVO  832   // 3*256 + 2*32

// shared layout (floats) — exactly 14336 floats = 57344 B (4 CTAs/SM)
// s_v is TRANSPOSED: svT[c][e], c=0..255 feature rows of 16 electrons,
// chunk-swizzled: chunk cc stored at (cc ^ ((c>>1)&3)).
#define OFF_SVT   0        // 256*16 = 4096
#define OFF_PV    4096     // 256*32 = 8192   (s_in + detS alias here)
#define OFF_MU    12288    // 256             (logd/sign/env alias here at the end)
#define OFF_MD    12544    // 256
#define OFF_PUT   12800    // 32*16 = 512 transposed (L0 4-wide pu also lives here)
#define OFF_PDT   13312    // 512
#define OFF_COM   13824    // 512             (r_s/a_s alias here early)
#define SMEM_FLOATS 14336
#define SMEM_BYTES  (SMEM_FLOATS * 4)

#define SWZC(row, cc) ((((cc) ^ (((row) >> 1) & 3))) << 2)

typedef unsigned long long u64;

__device__ __forceinline__ u64 fma2(u64 a, u64 b, u64 c) {
    u64 d;
    asm("fma.rn.f32x2 %0, %1, %2, %3;" : "=l"(d) : "l"(a), "l"(b), "l"(c));
    return d;
}
__device__ __forceinline__ u64 dup2(float x) {
    u64 d;
    asm("mov.b64 %0, {%1, %1};" : "=l"(d) : "f"(x));
    return d;
}
__device__ __forceinline__ float2 unpack2(u64 v) {
    float2 r;
    asm("mov.b64 {%0, %1}, %2;" : "=f"(r.x), "=f"(r.y) : "l"(v));
    return r;
}

__device__ __forceinline__ float tanh_fast(float x) {
    float e = __expf(2.0f * x);
    return 1.0f - __fdividef(2.0f, e + 1.0f);
}

__global__ void __launch_bounds__(256, 4) ansatz_kernel(
    const float* __restrict__ r,    const float* __restrict__ a,
    const float* __restrict__ sW0,  const float* __restrict__ sb0,
    const float* __restrict__ sW,   const float* __restrict__ sb,
    const float* __restrict__ pW0,  const float* __restrict__ pb0,
    const float* __restrict__ pW,   const float* __restrict__ pb,
    const float* __restrict__ vW,   const float* __restrict__ vb,
    const float* __restrict__ wuW,  const float* __restrict__ wub,
    const float* __restrict__ wdW,  const float* __restrict__ wdb,
    const float* __restrict__ wfW,  float* __restrict__ out)
{
    extern __shared__ float sm[];
    float* svT  = sm + OFF_SVT;
    float* p_v  = sm + OFF_PV;
    float* mu   = sm + OFF_MU;
    float* md   = sm + OFF_MD;
    float* puT  = sm + OFF_PUT;   // transposed [k][e] post-L0; 4-wide [e][4] at L0
    float* pdT  = sm + OFF_PDT;
    float* com  = sm + OFF_COM;

    float* s_in = sm + OFF_PV;          // alias, dead before p_v written
    float* r_s  = sm + OFF_COM;         // alias, dead before com written
    float* a_s  = sm + OFF_COM + 48;
    float* detS   = sm + OFF_PV;        // alias, p_v dead by orbital phase
    float* logd_s = sm + OFF_MU;
    float* sign_s = sm + OFF_MU + 32;
    float* env    = sm + OFF_MU + 64;

    const int t = threadIdx.x;
    const int b = blockIdx.x;

    if (t < 48)              r_s[t]      = r[b * 48 + t];
    if (t >= 64 && t < 76)   a_s[t - 64] = a[t - 64];
    __syncthreads();

    // ---------------- embedding: s_in ----------------
    {
        int e = t >> 4, f = t & 15, atom = f >> 2, comp = f & 3;
        float dx = r_s[e*3+0] - a_s[atom*3+0];
        float dy = r_s[e*3+1] - a_s[atom*3+1];
        float dz = r_s[e*3+2] - a_s[atom*3+2];
        float v;
        if      (comp == 0) v = dx;
        else if (comp == 1) v = dy;
        else if (comp == 2) v = dz;
        else                v = sqrtf(dx*dx + dy*dy + dz*dz);
        s_in[t] = v;
    }
    __syncthreads();

    // ---------------- stats for layer 0 (mu/md 16-wide; pu/pd 4-wide) ----------------
    if (t < 16) {
        float s = 0.f;
        #pragma unroll
        for (int e = 0; e < NU; e++) s += s_in[e*16 + t];
        mu[t] = s * 0.125f;
    } else if (t < 32) {
        int f = t - 16; float s = 0.f;
        #pragma unroll
        for (int e = NU; e < NE; e++) s += s_in[e*16 + f];
        md[f] = s * 0.125f;
    } else if (t < 160) {
        int idx = t - 32;
        int half = idx >> 6;
        idx &= 63;
        int j = idx >> 2, c = idx & 3;
        int ib = half * 8;
        float rjx = r_s[j*3+0], rjy = r_s[j*3+1], rjz = r_s[j*3+2];
        float s = 0.f;
        #pragma unroll
        for (int ii = 0; ii < 8; ii++) {
            int i = ib + ii;
            float dx = rjx - r_s[i*3+0];
            float dy = rjy - r_s[i*3+1];
            float dz = rjz - r_s[i*3+2];
            float v;
            if      (c == 0) v = dx;
            else if (c == 1) v = dy;
            else if (c == 2) v = dz;
            else {
                float o = (i == j) ? 1.f : 0.f;
                float ex = dx + o, ey = dy + o, ez = dz + o;
                v = sqrtf(ex*ex + ey*ey + ez*ez);
            }
            s += v;
        }
        if (half == 0) puT[j*4 + c] = s * 0.125f;   // 4-wide L0 layout
        else           pdT[j*4 + c] = s * 0.125f;
    }
    __syncthreads();

    // ---------------- layer 0, s-stream (writes transposed svT) ----------------
    float smu, smd;
    {
        const int c = t;
        float common = sb0[c];
        #pragma unroll
        for (int k = 0; k < 16; k++)
            common += mu[k] * sW0[(16 + k)*NSV + c] + md[k] * sW0[(32 + k)*NSV + c];
        float acc[NE];
        #pragma unroll
        for (int e = 0; e < NE; e++) acc[e] = 0.f;
        #pragma unroll
        for (int k = 0; k < 16; k++) {
            float wv = sW0[k*NSV + c];
            #pragma unroll
            for (int e = 0; e < NE; e++) acc[e] += s_in[e*16 + k] * wv;
        }
        #pragma unroll
        for (int k = 0; k < 4; k++) {
            float wA = sW0[(48 + k)*NSV + c];
            float wB = sW0[(52 + k)*NSV + c];
            #pragma unroll
            for (int e = 0; e < NE; e++)
                acc[e] += puT[e*4 + k] * wA + pdT[e*4 + k] * wB;
        }
        smu = 0.f; smd = 0.f;
        #pragma unroll
        for (int cc = 0; cc < 4; cc++) {
            float4 q;
            q.x = tanh_fast(acc[4*cc+0] + common);
            q.y = tanh_fast(acc[4*cc+1] + common);
            q.z = tanh_fast(acc[4*cc+2] + common);
            q.w = tanh_fast(acc[4*cc+3] + common);
            if (cc < 2) smu += q.x + q.y + q.z + q.w;
            else        smd += q.x + q.y + q.z + q.w;
            *(float4*)(svT + c*16 + SWZC(c, cc)) = q;
        }
    }
    __syncthreads();   // s_in reads done; p_v + transposed puT may be written

    // ---------------- layer 0, p-stream (writes p_v + transposed puT/pdT) ----------------
    {
        const int c2 = t & 31, wp = t >> 5;
        float w0 = pW0[0*NPV + c2], w1 = pW0[1*NPV + c2];
        float w2 = pW0[2*NPV + c2], w3 = pW0[3*NPV + c2];
        const float pbias = pb0[c2];
        float puA = 0.f, puB = 0.f, pdA = 0.f, pdB = 0.f;
        for (int pr = wp; pr < 256; pr += 8) {
            int i = pr >> 4, j = pr & 15;
            float dx = r_s[j*3+0] - r_s[i*3+0];
            float dy = r_s[j*3+1] - r_s[i*3+1];
            float dz = r_s[j*3+2] - r_s[i*3+2];
            float o = (i == j) ? 1.f : 0.f;
            float ex = dx + o, ey = dy + o, ez = dz + o;
            float len = sqrtf(ex*ex + ey*ey + ez*ez);
            float v = tanh_fast(pbias + dx*w0 + dy*w1 + dz*w2 + len*w3);
            p_v[pr*NPV + c2] = v;
            bool jA = ((pr >> 3) & 1) == 0;
            if (i < NU) { if (jA) puA += v; else puB += v; }
            else        { if (jA) pdA += v; else pdB += v; }
        }
        mu[t] = smu * 0.125f;
        md[t] = smd * 0.125f;
        __syncthreads();   // 4-wide pu/pd reads (L0 s-stream) fully done above
        puT[c2*16 + wp]     = puA * 0.125f;   // transposed [k=c2][e=wp]
        puT[c2*16 + wp + 8] = puB * 0.125f;
        pdT[c2*16 + wp]     = pdA * 0.125f;
        pdT[c2*16 + wp + 8] = pdB * 0.125f;
    }
    __syncthreads();

    // ---------------- residual layers + final v layer ----------------
    const int eh    = t >> 7;          // electron half (warp-uniform)
    const int cp    = t & 127;
    const int cA    = 2 * cp;          // 2 adjacent feature cols per thread
    const int ch0   = 2*eh, ch1 = 2*eh + 1;   // electron chunks of this half
    // common-matvec mapping (unchanged from R6)
    const int bh    = t >> 7;
    const int ckh   = t & 1;
    const int ccA   = ((t >> 1) & 63) * 4;

    for (int L = 0; L <= NFB; L++) {
        const bool isV = (L == NFB);
        const float* W    = isV ? vW : (sW + (size_t)L * SVO * NSV);
        const float* bias = isV ? vb : (sb + L * NSV);

        float puA = 0.f, puB = 0.f, pdA = 0.f, pdB = 0.f;
        if (!isV) {
            // p-stream residual layer (lane-private columns, in-place)
            const int c2 = t & 31, wp = t >> 5;
            const float* PW = pW + L * NPV * NPV + c2;
            float pw[32];
            #pragma unroll
            for (int k = 0; k < 32; k++) pw[k] = PW[k*NPV];
            const float pbias = pb[L*NPV + c2];
            for (int pr = wp; pr < 256; pr += 8) {
                float pacc = pbias;
                #pragma unroll
                for (int k = 0; k < 32; k += 4) {
                    float4 v4 = *(const float4*)(p_v + pr*NPV + k);
                    pacc += v4.x*pw[k] + v4.y*pw[k+1] + v4.z*pw[k+2] + v4.w*pw[k+3];
                }
                float v = tanh_fast(pacc) + p_v[pr*NPV + c2];
                p_v[pr*NPV + c2] = v;
                bool jA = ((pr >> 3) & 1) == 0;
                if ((pr >> 4) < NU) { if (jA) puA += v; else puB += v; }
                else                { if (jA) pdA += v; else pdB += v; }
            }
        }

        // ---- common matvec (scalar, R6 scheme) ----
        {
            const float* statv = (bh ? md : mu) + ckh * 128;
            const float* Wblk  = W + (size_t)(256 + bh*256 + ckh*128) * NSV + ccA;
            float c4x = 0.f, c4y = 0.f, c4z = 0.f, c4w = 0.f;
            for (int k = 0; k < 128; k += 4) {
                float4 m4 = *(const float4*)(statv + k);
                float4 w0 = *(const float4*)(Wblk + (k+0)*NSV);
                float4 w1 = *(const float4*)(Wblk + (k+1)*NSV);
                float4 w2 = *(const float4*)(Wblk + (k+2)*NSV);
                float4 w3 = *(const float4*)(Wblk + (k+3)*NSV);
                c4x += m4.x*w0.x + m4.y*w1.x + m4.z*w2.x + m4.w*w3.x;
                c4y += m4.x*w0.y + m4.y*w1.y + m4.z*w2.y + m4.w*w3.y;
                c4z += m4.x*w0.z + m4.y*w1.z + m4.z*w2.z + m4.w*w3.z;
                c4w += m4.x*w0.w + m4.y*w1.w + m4.z*w2.w + m4.w*w3.w;
            }
            c4x += __shfl_xor_sync(0xffffffffu, c4x, 1);
            c4y += __shfl_xor_sync(0xffffffffu, c4y, 1);
            c4z += __shfl_xor_sync(0xffffffffu, c4z, 1);
            c4w += __shfl_xor_sync(0xffffffffu, c4w, 1);
            if (ckh == 0) {
                float vx = c4x, vy = c4y;
                if (bh == 0) { vx += bias[ccA];   vy += bias[ccA+1]; }
                float2 cv; cv.x = vx; cv.y = vy;
                *(float2*)(com + bh*256 + ccA) = cv;
            } else {
                float vz = c4z, vw = c4w;
                if (bh == 0) { vz += bias[ccA+2]; vw += bias[ccA+3]; }
                float2 cv; cv.x = vz; cv.y = vw;
                *(float2*)(com + bh*256 + ccA + 2) = cv;
            }
        }

        // ---- main GEMM: packed f32x2 over electron pairs; 2 cols ----
        u64 ac00 = 0, ac01 = 0, ac10 = 0, ac11 = 0,
            ac20 = 0, ac21 = 0, ac30 = 0, ac31 = 0;   // [pair][col]
        {
            const float* Wc = W + cA;
            #pragma unroll 4
            for (int k = 0; k < 256; k++) {
                float2 wv = *(const float2*)(Wc + k*NSV);
                u64 dw0 = dup2(wv.x), dw1 = dup2(wv.y);
                ulonglong2 A = *(const ulonglong2*)(svT + k*16 + SWZC(k, ch0));
                ulonglong2 B = *(const ulonglong2*)(svT + k*16 + SWZC(k, ch1));
                ac00 = fma2(A.x, dw0, ac00);  ac01 = fma2(A.x, dw1, ac01);
                ac10 = fma2(A.y, dw0, ac10);  ac11 = fma2(A.y, dw1, ac11);
                ac20 = fma2(B.x, dw0, ac20);  ac21 = fma2(B.x, dw1, ac21);
                ac30 = fma2(B.y, dw0, ac30);  ac31 = fma2(B.y, dw1, ac31);
            }
        }
        // ---- pair blocks (transposed puT/pdT, same packing) ----
        {
            const float* Wp = W + (size_t)768*NSV + cA;
            #pragma unroll 4
            for (int k = 0; k < 32; k++) {
                float2 wv = *(const float2*)(Wp + k*NSV);
                u64 dw0 = dup2(wv.x), dw1 = dup2(wv.y);
                ulonglong2 A = *(const ulonglong2*)(puT + k*16 + ch0*4);
                ulonglong2 B = *(const ulonglong2*)(puT + k*16 + ch1*4);
                ac00 = fma2(A.x, dw0, ac00);  ac01 = fma2(A.x, dw1, ac01);
                ac10 = fma2(A.y, dw0, ac10);  ac11 = fma2(A.y, dw1, ac11);
                ac20 = fma2(B.x, dw0, ac20);  ac21 = fma2(B.x, dw1, ac21);
                ac30 = fma2(B.y, dw0, ac30);  ac31 = fma2(B.y, dw1, ac31);
            }
        }
        {
            const float* Wp = W + (size_t)800*NSV + cA;
            #pragma unroll 4
            for (int k = 0; k < 32; k++) {
                float2 wv = *(const float2*)(Wp + k*NSV);
                u64 dw0 = dup2(wv.x), dw1 = dup2(wv.y);
                ulonglong2 A = *(const ulonglong2*)(pdT + k*16 + ch0*4);
                ulonglong2 B = *(const ulonglong2*)(pdT + k*16 + ch1*4);
                ac00 = fma2(A.x, dw0, ac00);  ac01 = fma2(A.x, dw1, ac01);
                ac10 = fma2(A.y, dw0, ac10);  ac11 = fma2(A.y, dw1, ac11);
                ac20 = fma2(B.x, dw0, ac20);  ac21 = fma2(B.x, dw1, ac21);
                ac30 = fma2(B.y, dw0, ac30);  ac31 = fma2(B.y, dw1, ac31);
            }
        }

        __syncthreads();   // svT/puT/pdT/mu/md reads + com writes complete

        // ---- writeback: unpack pairs, tanh(+residual), store 2 rows ----
        {
            float2 cm0 = *(const float2*)(com + cA);
            float2 cm1 = *(const float2*)(com + 256 + cA);
            const float cmA = cm0.x + cm1.x;
            const float cmB = cm0.y + cm1.y;
            float nA[8], nB[8];
            { float2 u = unpack2(ac00); nA[0]=u.x+cmA; nA[1]=u.y+cmA; }
            { float2 u = unpack2(ac10); nA[2]=u.x+cmA; nA[3]=u.y+cmA; }
            { float2 u = unpack2(ac20); nA[4]=u.x+cmA; nA[5]=u.y+cmA; }
            { float2 u = unpack2(ac30); nA[6]=u.x+cmA; nA[7]=u.y+cmA; }
            { float2 u = unpack2(ac01); nB[0]=u.x+cmB; nB[1]=u.y+cmB; }
            { float2 u = unpack2(ac11); nB[2]=u.x+cmB; nB[3]=u.y+cmB; }
            { float2 u = unpack2(ac21); nB[4]=u.x+cmB; nB[5]=u.y+cmB; }
            { float2 u = unpack2(ac31); nB[6]=u.x+cmB; nB[7]=u.y+cmB; }
            float* row0 = svT + cA*16;
            float* row1 = svT + (cA+1)*16;
            if (!isV) {
                float4 o00 = *(const float4*)(row0 + SWZC(cA,   ch0));
                float4 o01 = *(const float4*)(row0 + SWZC(cA,   ch1));
                float4 o10 = *(const float4*)(row1 + SWZC(cA+1, ch0));
                float4 o11 = *(const float4*)(row1 + SWZC(cA+1, ch1));
                float4 q;
                q.x = tanh_fast(nA[0]) + o00.x; q.y = tanh_fast(nA[1]) + o00.y;
                q.z = tanh_fast(nA[2]) + o00.z; q.w = tanh_fast(nA[3]) + o00.w;
                *(float4*)(row0 + SWZC(cA, ch0)) = q;
                q.x = tanh_fast(nA[4]) + o01.x; q.y = tanh_fast(nA[5]) + o01.y;
                q.z = tanh_fast(nA[6]) + o01.z; q.w = tanh_fast(nA[7]) + o01.w;
                *(float4*)(row0 + SWZC(cA, ch1)) = q;
                q.x = tanh_fast(nB[0]) + o10.x; q.y = tanh_fast(nB[1]) + o10.y;
                q.z = tanh_fast(nB[2]) + o10.z; q.w = tanh_fast(nB[3]) + o10.w;
                *(float4*)(row1 + SWZC(cA+1, ch0)) = q;
                q.x = tanh_fast(nB[4]) + o11.x; q.y = tanh_fast(nB[5]) + o11.y;
                q.z = tanh_fast(nB[6]) + o11.z; q.w = tanh_fast(nB[7]) + o11.w;
                *(float4*)(row1 + SWZC(cA+1, ch1)) = q;
                // deferred pu/pd stores (transposed)
                const int c2 = t & 31, wp = t >> 5;
                puT[c2*16 + wp]     = puA * 0.125f;
                puT[c2*16 + wp + 8] = puB * 0.125f;
                pdT[c2*16 + wp]     = pdA * 0.125f;
                pdT[c2*16 + wp + 8] = pdB * 0.125f;
            } else {
                float4 q;
                q.x = tanh_fast(nA[0]); q.y = tanh_fast(nA[1]);
                q.z = tanh_fast(nA[2]); q.w = tanh_fast(nA[3]);
                *(float4*)(row0 + SWZC(cA, ch0)) = q;
                q.x = tanh_fast(nA[4]); q.y = tanh_fast(nA[5]);
                q.z = tanh_fast(nA[6]); q.w = tanh_fast(nA[7]);
                *(float4*)(row0 + SWZC(cA, ch1)) = q;
                q.x = tanh_fast(nB[0]); q.y = tanh_fast(nB[1]);
                q.z = tanh_fast(nB[2]); q.w = tanh_fast(nB[3]);
                *(float4*)(row1 + SWZC(cA+1, ch0)) = q;
                q.x = tanh_fast(nB[4]); q.y = tanh_fast(nB[5]);
                q.z = tanh_fast(nB[6]); q.w = tanh_fast(nB[7]);
                *(float4*)(row1 + SWZC(cA+1, ch1)) = q;
                if (t < 16) {   // env recompute (mu region dead now)
                    const float* rg = r + b*48 + t*3;
                    float ex = rg[0], ey = rg[1], ez = rg[2];
                    float s = 0.f;
                    #pragma unroll
                    for (int atom = 0; atom < NA; atom++) {
                        float dx = ex - a[atom*3+0];
                        float dy = ey - a[atom*3+1];
                        float dz = ez - a[atom*3+2];
                        s += __expf(-sqrtf(dx*dx + dy*dy + dz*dz));
                    }
                    env[t] = s;
                }
            }
        }
        __syncthreads();

        if (!isV) {
            // ---- mu/md stats pass: thread t = feature row t ----
            const int c = t;
            float4 q0 = *(const float4*)(svT + c*16 + SWZC(c, 0));
            float4 q1 = *(const float4*)(svT + c*16 + SWZC(c, 1));
            float4 q2 = *(const float4*)(svT + c*16 + SWZC(c, 2));
            float4 q3 = *(const float4*)(svT + c*16 + SWZC(c, 3));
            mu[c] = (q0.x+q0.y+q0.z+q0.w + q1.x+q1.y+q1.z+q1.w) * 0.125f;
            md[c] = (q2.x+q2.y+q2.z+q2.w + q3.x+q3.y+q3.z+q3.w) * 0.125f;
            __syncthreads();
        }
    }
    // p_v dead; detS aliases its storage.

    // ---------------- orbitals: 1 col/thread, packed electron pairs ----------------
    {
        const int osp  = t >> 7;          // spin (warp-uniform)
        const int ocol = t & 127;
        const float* W    = osp ? wdW : wuW;
        const float* bias = osp ? wdb : wub;
        const int oc0 = 2*osp, oc1 = 2*osp + 1;   // electron chunks of this spin

        u64 oa0 = 0, oa1 = 0, oa2 = 0, oa3 = 0;
        const float* Wc2 = W + ocol;
        #pragma unroll 4
        for (int k = 0; k < 256; k++) {
            u64 dw = dup2(Wc2[k*128]);
            ulonglong2 A = *(const ulonglong2*)(svT + k*16 + SWZC(k, oc0));
            ulonglong2 B = *(const ulonglong2*)(svT + k*16 + SWZC(k, oc1));
            oa0 = fma2(A.x, dw, oa0);
            oa1 = fma2(A.y, dw, oa1);
            oa2 = fma2(B.x, dw, oa2);
            oa3 = fma2(B.y, dw, oa3);
        }
        float o[8];
        { float2 u = unpack2(oa0); o[0]=u.x; o[1]=u.y; }
        { float2 u = unpack2(oa1); o[2]=u.x; o[3]=u.y; }
        { float2 u = unpack2(oa2); o[4]=u.x; o[5]=u.y; }
        { float2 u = unpack2(oa3); o[6]=u.x; o[7]=u.y; }
        const int d = ocol & 15, j = ocol >> 4;
        const int detIdx = osp * NDET + d;
        const float bs = bias[ocol];
        #pragma unroll
        for (int ii = 0; ii < 8; ii++)
            detS[detIdx*65 + ii*8 + j] = (o[ii] + bs) * env[osp*8 + ii];
    }
    __syncthreads();

    // ---------------- slogdet: 8x8 LU with partial pivoting ----------------
    if (t < 32) {
        float* M = detS + t * 65;
        float sg = 1.f, ld = 0.f;
        for (int k = 0; k < 8; k++) {
            int p = k; float best = fabsf(M[k*8 + k]);
            for (int rr2 = k + 1; rr2 < 8; rr2++) {
                float v = fabsf(M[rr2*8 + k]);
                if (v > best) { best = v; p = rr2; }
            }
            if (p != k) {
                for (int cc = 0; cc < 8; cc++) {
                    float tmp = M[k*8 + cc]; M[k*8 + cc] = M[p*8 + cc]; M[p*8 + cc] = tmp;
                }
                sg = -sg;
            }
            float piv = M[k*8 + k];
            if (piv < 0.f) sg = -sg;
            ld += logf(fabsf(piv));
            float inv = 1.f / piv;
            for (int rr2 = k + 1; rr2 < 8; rr2++) {
                float f = M[rr2*8 + k] * inv;
                for (int cc = k + 1; cc < 8; cc++) M[rr2*8 + cc] -= f * M[k*8 + cc];
            }
        }
        logd_s[t] = ld; sign_s[t] = sg;
    }
    __syncthreads();

    // ---------------- combine ----------------
    if (t == 0) {
        float lds[NDET], sgs[NDET], m = -1e30f;
        #pragma unroll
        for (int d = 0; d < NDET; d++) {
            lds[d] = logd_s[d] + logd_s[NDET + d];
            sgs[d] = sign_s[d] * sign_s[NDET + d];
            if (lds[d] > m) m = lds[d];
        }
        float sum = 0.f;
        #pragma unroll
        for (int d = 0; d < NDET; d++)
            sum += sgs[d] * expf(lds[d] - m) * wfW[d];
        out[b] = logf(fabsf(sum)) + m;
    }
}

extern "C" void kernel_launch(void* const* d_in, const int* in_sizes, int n_in,
                              void* d_out, int out_size)
{
    const float* r   = (const float*)d_in[0];
    const float* a   = (const float*)d_in[1];
    const float* sW0 = (const float*)d_in[2];
    const float* sb0 = (const float*)d_in[3];
    const float* sW  = (const float*)d_in[4];
    const float* sb  = (const float*)d_in[5];
    const float* pW0 = (const float*)d_in[6];
    const float* pb0 = (const float*)d_in[7];
    const float* pW  = (const float*)d_in[8];
    const float* pb  = (const float*)d_in[9];
    const float* vW  = (const float*)d_in[10];
    const float* vb  = (const float*)d_in[11];
    const float* wuW = (const float*)d_in[12];
    const float* wub = (const float*)d_in[13];
    const float* wdW = (const float*)d_in[14];
    const float* wdb = (const float*)d_in[15];
    const float* wfW = (const float*)d_in[16];
    float* out = (float*)d_out;

    const int B = in_sizes[0] / (NE * 3);

    cudaFuncSetAttribute(ansatz_kernel,
                         cudaFuncAttributeMaxDynamicSharedMemorySize, SMEM_BYTES);
    ansatz_kernel<<<B, 256, SMEM_BYTES>>>(r, a, sW0, sb0, sW, sb, pW0, pb0,
                                          pW, pb, vW, vb, wuW, wub, wdW, wdb,
                                          wfW, out);
}